// round 12
// baseline (speedup 1.0000x reference)
#include <cuda_runtime.h>

#define Ww 112
#define NP (112*112)
#define NCH 64
#define G4 28                 // float4 groups per row

__device__ __forceinline__ float rcpa(float x) {
    float y; asm("rcp.approx.f32 %0, %1;" : "=f"(y) : "f"(x)); return y;
}

__device__ __forceinline__ float4 pw4(float4 v, float p, bool p2) {
    float4 r;
    if (p2) { r.x=v.x*v.x; r.y=v.y*v.y; r.z=v.z*v.z; r.w=v.w*v.w; }
    else    { r.x=__powf(v.x,p); r.y=__powf(v.y,p);
              r.z=__powf(v.z,p); r.w=__powf(v.w,p); }
    return r;
}

// 4 outputs with ONE MUFU.RCP
__device__ __forceinline__ float4 norm4v(float4 n, float d0, float d1,
                                         float d2, float d3,
                                         float wgt, float bs) {
    const float d01 = d0*d1, d23 = d2*d3;
    const float r   = rcpa(d01*d23);
    const float r01 = r*d23, r23 = r*d01;
    float4 o;
    o.x = fmaf(wgt*n.x, r01*d1, bs);
    o.y = fmaf(wgt*n.y, r01*d0, bs);
    o.z = fmaf(wgt*n.z, r23*d3, bs);
    o.w = fmaf(wgt*n.w, r23*d2, bs);
    return o;
}

__global__ __launch_bounds__(256, 4)
void bionorm_kernel(const float* __restrict__ x,
                    const float* __restrict__ sigma,
                    const float* __restrict__ pow_p,
                    const float* __restrict__ ker,
                    const float* __restrict__ weight,
                    const float* __restrict__ bias,
                    float* __restrict__ out)
{
    const int plane = blockIdx.x;           // b*C + c
    const int c     = plane & (NCH - 1);
    const int warp  = threadIdx.x >> 5;
    const int lane  = threadIdx.x & 31;
    const int xl    = min(lane, 27);        // owned float4 group
    const bool act  = lane < 28;

    const float4* __restrict__ xp4 =
        reinterpret_cast<const float4*>(x + (size_t)plane * NP);
    float4* __restrict__ po4 =
        reinterpret_cast<float4*>(out + (size_t)plane * NP);

    const float p  = pow_p[c];
    const bool  p2 = (p == 2.0f);

    // ---- per-channel params: rank-1 / unit-rk / uniform-ck detection ----
    const float* __restrict__ kerg = ker + c * 25;
    float maxa = 0.0f, best = -1.0f; int pi = 0;
#pragma unroll
    for (int i = 0; i < 25; i++) {
        const float a = fabsf(__ldg(kerg + i));
        maxa = fmaxf(maxa, a);
        if (a > best) { best = a; pi = i; }
    }
    const int i0 = pi / 5, j0 = pi - i0 * 5;

    float rk[5], ck[5];
    int mode = 2;          // 0: unit row weights (slide)  1: separable  2: general
    bool uni = false;      // ck all equal (sliding h)
    if (maxa > 0.0f) {
        const float inv = 1.0f / __ldg(kerg + pi);
#pragma unroll
        for (int i = 0; i < 5; i++) rk[i] = __ldg(kerg + i*5 + j0) * inv;
#pragma unroll
        for (int j = 0; j < 5; j++) ck[j] = __ldg(kerg + i0*5 + j);
        bool sep = true;
        const float tol = 1e-6f * maxa;
#pragma unroll
        for (int i = 0; i < 5; i++)
#pragma unroll
            for (int j = 0; j < 5; j++)
                if (fabsf(fmaf(-rk[i], ck[j], __ldg(kerg + i*5 + j))) > tol)
                    sep = false;
        if (sep) {
            bool unit = true;
#pragma unroll
            for (int i = 0; i < 5; i++)
                if (fabsf(rk[i] - 1.0f) > 1e-6f) unit = false;
            mode = unit ? 0 : 1;
            uni = true;
            const float utol = 1e-6f * fabsf(ck[0]);
#pragma unroll
            for (int j = 1; j < 5; j++)
                if (fabsf(ck[j] - ck[0]) > utol) uni = false;
        }
    } else {
#pragma unroll
        for (int i = 0; i < 5; i++) { rk[i] = 1.0f; ck[i] = 0.0f; }
        mode = 0; uni = true;
    }
    const float w25 = ck[0];
    const float k0 = ck[0], k1 = ck[1], k2 = ck[2], k3 = ck[3], k4 = ck[4];

    const float sgm = sigma[c];
    const float sp  = p2 ? sgm*sgm : __powf(sgm, p);
    const float wgt = weight[c];
    const float bs  = bias[c];

    const int y0 = warp * 14;                 // this warp's 14-row strip

    if (mode == 0) {
        // ===== hot path: register 5-row history, 1 LDG.128 per row =====
        float4 H0, H1, H2, H3, H4;            // window rows cy-2..cy+2 (pw'd)
        float t0, t1, t2, t3;                 // vertical column sums

        auto pwl = [&](int row) -> float4 {
            return pw4(__ldg(&xp4[row * G4 + xl]), p, p2);
        };
        auto sumt = [&] {
            t0 = ((H0.x + H1.x) + (H2.x + H3.x)) + H4.x;
            t1 = ((H0.y + H1.y) + (H2.y + H3.y)) + H4.y;
            t2 = ((H0.z + H1.z) + (H2.z + H3.z)) + H4.z;
            t3 = ((H0.w + H1.w) + (H2.w + H3.w)) + H4.w;
        };
        auto slide = [&](int rowin) {
            const float4 e = pwl(rowin);
            t0 += e.x - H0.x; t1 += e.y - H0.y;
            t2 += e.z - H0.z; t3 += e.w - H0.w;
            H0 = H1; H1 = H2; H2 = H3; H3 = H4; H4 = e;
        };
        auto emit = [&](int y, float4 n) {
            const float am2 = __shfl_up_sync(0xFFFFFFFFu, t2, 1);
            const float am1 = __shfl_up_sync(0xFFFFFFFFu, t3, 1);
            const float a4  = __shfl_down_sync(0xFFFFFFFFu, t0, 1);
            const float a5  = __shfl_down_sync(0xFFFFFFFFu, t1, 1);
            float h0, h1, h2, h3;
            if (uni) {
                h0 = ((am2 + am1) + (t0 + t1)) + t2;
                h1 = h0 - am2 + t3;
                h2 = h1 - am1 + a4;
                h3 = h2 - t0 + a5;
            } else {
                h0 = k0*am2 + k1*am1 + k2*t0 + k3*t1 + k4*t2;
                h1 = k0*am1 + k1*t0  + k2*t1 + k3*t2 + k4*t3;
                h2 = k0*t0  + k1*t1  + k2*t2 + k3*t3 + k4*a4;
                h3 = k0*t1  + k1*t2  + k2*t3 + k3*a4 + k4*a5;
            }
            if (lane == 0)  { h0 = h2; h1 = h2; }   // x-replicate left
            if (lane == 27) { h2 = h1; h3 = h1; }   // x-replicate right
            float d0, d1, d2, d3;
            if (uni) {
                d0 = fmaf(w25, h0, sp); d1 = fmaf(w25, h1, sp);
                d2 = fmaf(w25, h2, sp); d3 = fmaf(w25, h3, sp);
            } else {
                d0 = sp + h0; d1 = sp + h1; d2 = sp + h2; d3 = sp + h3;
            }
            if (act)
                po4[y * G4 + xl] = norm4v(n, d0, d1, d2, d3, wgt, bs);
        };

        if (warp == 0) {
            // rows 0..13; cy=2 for y<=2 (no slide), numerators H0,H1,H2
            H0 = pwl(0); H1 = pwl(1); H2 = pwl(2); H3 = pwl(3); H4 = pwl(4);
            sumt();
            emit(0, H0);
            emit(1, H1);
            emit(2, H2);
#pragma unroll
            for (int i = 3; i < 14; i++) { slide(i + 2); emit(i, H2); }
        } else if (warp == 7) {
            // rows 98..111; slides until cy=109, then numerators H3,H4
            H0 = pwl(96); H1 = pwl(97); H2 = pwl(98); H3 = pwl(99); H4 = pwl(100);
            sumt();
            emit(98, H2);
#pragma unroll
            for (int i = 1; i < 12; i++) { slide(98 + i + 2); emit(98 + i, H2); }
            emit(110, H3);
            emit(111, H4);
        } else {
            // interior strips: slide every row after the first
            H0 = pwl(y0-2); H1 = pwl(y0-1); H2 = pwl(y0);
            H3 = pwl(y0+1); H4 = pwl(y0+2);
            sumt();
            emit(y0, H2);
#pragma unroll
            for (int i = 1; i < 14; i++) { slide(y0 + i + 2); emit(y0 + i, H2); }
        }
        return;
    }

    // ===== cold paths (modes 1, 2): correctness fallback =====
    int cy = min(max(y0, 2), 109);
#pragma unroll 1
    for (int y = y0; y < y0 + 14; y++) {
        const int cyn = min(max(y, 2), 109);
        float d0, d1, d2, d3;

        if (mode == 1) {
            float t0 = 0, t1 = 0, t2 = 0, t3 = 0;
#pragma unroll
            for (int rr = 0; rr < 5; rr++) {
                float4 q = pw4(xp4[(cyn - 2 + rr) * G4 + xl], p, p2);
                const float w = rk[rr];
                t0 = fmaf(w, q.x, t0); t1 = fmaf(w, q.y, t1);
                t2 = fmaf(w, q.z, t2); t3 = fmaf(w, q.w, t3);
            }
            const float am2 = __shfl_up_sync(0xFFFFFFFFu, t2, 1);
            const float am1 = __shfl_up_sync(0xFFFFFFFFu, t3, 1);
            const float a4  = __shfl_down_sync(0xFFFFFFFFu, t0, 1);
            const float a5  = __shfl_down_sync(0xFFFFFFFFu, t1, 1);
            float h0 = k0*am2 + k1*am1 + k2*t0 + k3*t1 + k4*t2;
            float h1 = k0*am1 + k1*t0  + k2*t1 + k3*t2 + k4*t3;
            float h2 = k0*t0  + k1*t1  + k2*t2 + k3*t3 + k4*a4;
            float h3 = k0*t1  + k1*t2  + k2*t3 + k3*a4 + k4*a5;
            if (lane == 0)  { h0 = h2; h1 = h2; }
            if (lane == 27) { h2 = h1; h3 = h1; }
            d0 = sp + h0; d1 = sp + h1; d2 = sp + h2; d3 = sp + h3;
        } else {
            const float* xs = reinterpret_cast<const float*>(xp4);
            float dd[4];
#pragma unroll
            for (int j = 0; j < 4; j++) {
                const int cx = min(max(4*xl + j, 2), 109);
                float a = 0.0f;
                for (int rr = 0; rr < 5; rr++)
                    for (int tt = 0; tt < 5; tt++) {
                        float v = __ldg(xs + (cyn-2+rr)*Ww + (cx-2+tt));
                        float xv = p2 ? v*v : __powf(v, p);
                        a = fmaf(__ldg(kerg + rr*5 + tt), xv, a);
                    }
                dd[j] = sp + a;
            }
            d0 = dd[0]; d1 = dd[1]; d2 = dd[2]; d3 = dd[3];
        }
        cy = cyn;

        const float4 n = pw4(xp4[y * G4 + xl], p, p2);
        if (act)
            po4[y * G4 + xl] = norm4v(n, d0, d1, d2, d3, wgt, bs);
    }
}

extern "C" void kernel_launch(void* const* d_in, const int* in_sizes, int n_in,
                              void* d_out, int out_size)
{
    const float* x      = (const float*)d_in[0];
    const float* sigma  = (const float*)d_in[1];
    const float* pow_p  = (const float*)d_in[2];
    const float* ker    = (const float*)d_in[3];
    const float* weight = (const float*)d_in[4];
    const float* bias   = (const float*)d_in[5];
    float* out = (float*)d_out;

    bionorm_kernel<<<32 * NCH, 256>>>(x, sigma, pow_p, ker,
                                      weight, bias, out);
}

// round 14
// speedup vs baseline: 1.1647x; 1.1647x over previous
#include <cuda_runtime.h>

#define Ww 112
#define NP (112*112)
#define NCH 64
#define G4 28                 // float4 groups per row

__device__ __forceinline__ float rcpa(float x) {
    float y; asm("rcp.approx.f32 %0, %1;" : "=f"(y) : "f"(x)); return y;
}

__device__ __forceinline__ float4 pw4(float4 v, float p, bool p2) {
    float4 r;
    if (p2) { r.x=v.x*v.x; r.y=v.y*v.y; r.z=v.z*v.z; r.w=v.w*v.w; }
    else    { r.x=__powf(v.x,p); r.y=__powf(v.y,p);
              r.z=__powf(v.z,p); r.w=__powf(v.w,p); }
    return r;
}

// 4 outputs with ONE MUFU.RCP
__device__ __forceinline__ float4 norm4v(float4 n, float d0, float d1,
                                         float d2, float d3,
                                         float wgt, float bs) {
    const float d01 = d0*d1, d23 = d2*d3;
    const float r   = rcpa(d01*d23);
    const float r01 = r*d23, r23 = r*d01;
    float4 o;
    o.x = fmaf(wgt*n.x, r01*d1, bs);
    o.y = fmaf(wgt*n.y, r01*d0, bs);
    o.z = fmaf(wgt*n.z, r23*d3, bs);
    o.w = fmaf(wgt*n.w, r23*d2, bs);
    return o;
}

__global__ __launch_bounds__(128, 10)
void bionorm_kernel(const float* __restrict__ x,
                    const float* __restrict__ sigma,
                    const float* __restrict__ pow_p,
                    const float* __restrict__ ker,
                    const float* __restrict__ weight,
                    const float* __restrict__ bias,
                    float* __restrict__ out)
{
    const int bid   = blockIdx.x;
    const int plane = bid >> 1;             // b*C + c
    const int half  = bid & 1;
    const int c     = plane & (NCH - 1);
    const int warp  = threadIdx.x >> 5;     // 0..3
    const int lane  = threadIdx.x & 31;
    const int xl    = min(lane, 27);        // owned float4 group
    const bool act  = lane < 28;

    const float4* __restrict__ xp4 =
        reinterpret_cast<const float4*>(x + (size_t)plane * NP);
    float4* __restrict__ po4 =
        reinterpret_cast<float4*>(out + (size_t)plane * NP);

    const float p  = pow_p[c];
    const bool  p2 = (p == 2.0f);

    // ---- per-channel params: rank-1 / unit-rk / uniform-ck detection ----
    const float* __restrict__ kerg = ker + c * 25;
    float maxa = 0.0f, best = -1.0f; int pi = 0;
#pragma unroll
    for (int i = 0; i < 25; i++) {
        const float a = fabsf(__ldg(kerg + i));
        maxa = fmaxf(maxa, a);
        if (a > best) { best = a; pi = i; }
    }
    const int i0 = pi / 5, j0 = pi - i0 * 5;

    float rk[5], ck[5];
    int mode = 2;          // 0: unit row weights (slide)  1: separable  2: general
    bool uni = false;      // ck all equal (sliding h)
    if (maxa > 0.0f) {
        const float inv = 1.0f / __ldg(kerg + pi);
#pragma unroll
        for (int i = 0; i < 5; i++) rk[i] = __ldg(kerg + i*5 + j0) * inv;
#pragma unroll
        for (int j = 0; j < 5; j++) ck[j] = __ldg(kerg + i0*5 + j);
        bool sep = true;
        const float tol = 1e-6f * maxa;
#pragma unroll
        for (int i = 0; i < 5; i++)
#pragma unroll
            for (int j = 0; j < 5; j++)
                if (fabsf(fmaf(-rk[i], ck[j], __ldg(kerg + i*5 + j))) > tol)
                    sep = false;
        if (sep) {
            bool unit = true;
#pragma unroll
            for (int i = 0; i < 5; i++)
                if (fabsf(rk[i] - 1.0f) > 1e-6f) unit = false;
            mode = unit ? 0 : 1;
            uni = true;
            const float utol = 1e-6f * fabsf(ck[0]);
#pragma unroll
            for (int j = 1; j < 5; j++)
                if (fabsf(ck[j] - ck[0]) > utol) uni = false;
        }
    } else {
#pragma unroll
        for (int i = 0; i < 5; i++) { rk[i] = 1.0f; ck[i] = 0.0f; }
        mode = 0; uni = true;
    }
    const float w25 = ck[0];
    const float k0 = ck[0], k1 = ck[1], k2 = ck[2], k3 = ck[3], k4 = ck[4];

    const float sgm = sigma[c];
    const float sp  = p2 ? sgm*sgm : __powf(sgm, p);
    const float wgt = weight[c];
    const float bs  = bias[c];

    const int y0 = half * 56 + warp * 14;     // this warp's 14-row strip
    int cy = min(max(y0, 2), 109);

    float t0 = 0, t1 = 0, t2 = 0, t3 = 0;     // vertical column sums
    if (mode == 0) {
#pragma unroll
        for (int rr = 0; rr < 5; rr++) {
            float4 q = pw4(xp4[(cy - 2 + rr) * G4 + xl], p, p2);
            t0 += q.x; t1 += q.y; t2 += q.z; t3 += q.w;
        }
    }

#pragma unroll 2
    for (int y = y0; y < y0 + 14; y++) {
        const int cyn = min(max(y, 2), 109);
        float d0, d1, d2, d3;

        if (mode < 2) {
            if (mode == 0) {
                if (cyn != cy) {               // warp-uniform branch
                    float4 e = pw4(xp4[(cyn + 2) * G4 + xl], p, p2);
                    float4 l = pw4(xp4[(cyn - 3) * G4 + xl], p, p2);
                    t0 += e.x - l.x; t1 += e.y - l.y;
                    t2 += e.z - l.z; t3 += e.w - l.w;
                    cy = cyn;
                }
            } else {                            // mode 1: rk-weighted rebuild
                t0 = t1 = t2 = t3 = 0.0f;
#pragma unroll
                for (int rr = 0; rr < 5; rr++) {
                    float4 q = pw4(xp4[(cyn - 2 + rr) * G4 + xl], p, p2);
                    const float w = rk[rr];
                    t0 = fmaf(w, q.x, t0); t1 = fmaf(w, q.y, t1);
                    t2 = fmaf(w, q.z, t2); t3 = fmaf(w, q.w, t3);
                }
            }

            // halo columns from neighbor lanes
            const float am2 = __shfl_up_sync(0xFFFFFFFFu, t2, 1);
            const float am1 = __shfl_up_sync(0xFFFFFFFFu, t3, 1);
            const float a4  = __shfl_down_sync(0xFFFFFFFFu, t0, 1);
            const float a5  = __shfl_down_sync(0xFFFFFFFFu, t1, 1);

            float h0, h1, h2, h3;
            if (uni) {                          // sliding plain 5-sums
                h0 = ((am2 + am1) + (t0 + t1)) + t2;
                h1 = h0 - am2 + t3;
                h2 = h1 - am1 + a4;
                h3 = h2 - t0 + a5;
            } else {                            // ck-weighted windows
                h0 = k0*am2 + k1*am1 + k2*t0 + k3*t1 + k4*t2;
                h1 = k0*am1 + k1*t0  + k2*t1 + k3*t2 + k4*t3;
                h2 = k0*t0  + k1*t1  + k2*t2 + k3*t3 + k4*a4;
                h3 = k0*t1  + k1*t2  + k2*t3 + k3*a4 + k4*a5;
            }
            if (lane == 0)  { h0 = h2; h1 = h2; }   // x-replicate left
            if (lane == 27) { h2 = h1; h3 = h1; }   // x-replicate right

            if (uni) {
                d0 = fmaf(w25, h0, sp); d1 = fmaf(w25, h1, sp);
                d2 = fmaf(w25, h2, sp); d3 = fmaf(w25, h3, sp);
            } else {
                d0 = sp + h0; d1 = sp + h1; d2 = sp + h2; d3 = sp + h3;
            }
        } else {
            // ---- mode 2: general 25-tap gather (cold, correctness only) ----
            const float* xs = reinterpret_cast<const float*>(xp4);
            float dd[4];
#pragma unroll
            for (int j = 0; j < 4; j++) {
                const int cx = min(max(4*xl + j, 2), 109);
                float a = 0.0f;
                for (int rr = 0; rr < 5; rr++)
                    for (int tt = 0; tt < 5; tt++) {
                        float v = __ldg(xs + (cyn-2+rr)*Ww + (cx-2+tt));
                        float xv = p2 ? v*v : __powf(v, p);
                        a = fmaf(__ldg(kerg + rr*5 + tt), xv, a);
                    }
                dd[j] = sp + a;
            }
            d0 = dd[0]; d1 = dd[1]; d2 = dd[2]; d3 = dd[3];
        }

        // numerator (L1-resident reload) + normalize + store
        const float4 n = pw4(xp4[y * G4 + xl], p, p2);
        if (act)
            po4[y * G4 + xl] = norm4v(n, d0, d1, d2, d3, wgt, bs);
    }
}

extern "C" void kernel_launch(void* const* d_in, const int* in_sizes, int n_in,
                              void* d_out, int out_size)
{
    const float* x      = (const float*)d_in[0];
    const float* sigma  = (const float*)d_in[1];
    const float* pow_p  = (const float*)d_in[2];
    const float* ker    = (const float*)d_in[3];
    const float* weight = (const float*)d_in[4];
    const float* bias   = (const float*)d_in[5];
    float* out = (float*)d_out;

    bionorm_kernel<<<32 * NCH * 2, 128>>>(x, sigma, pow_p, ker,
                                          weight, bias, out);
}